// round 15
// baseline (speedup 1.0000x reference)
#include <cuda_runtime.h>
#include <cuda_bf16.h>
#include <math.h>

#define NN     46080
#define EE     737280
#define BG     512
#define NODES  90
#define EPG    1440
#define HH     128
#define HL     64
#define XCP    192          // xc pairs per node (384 feats / 2)
#define LDA1P  (NODES*XCP)  // 17280 pairs per graph row

#define MPF 104             // fp32 stride for F scratch
#define NP  136             // u32 stride for Hb [k2][n]
#define SBL 132             // uint2 stride in k_lin1 As

// A  : row-major bf16 [m<96][k<96],  row stride 104 halfwords
// Ta : row-major bf16 [m<96][k<128], row stride 136 halfwords
#define OFF_A0  1024
#define SZ_A    (96*104*2)           // 19968 per plane
#define OFF_A1  (OFF_A0 + SZ_A)
#define OFF_U   (OFF_A1 + SZ_A)      // 40960
#define SZ_TA   (96*136*2)           // 26112 per plane
#define SZ_U    (2*SZ_TA)            // 52224
#define SMEMB   (OFF_U + SZ_U + 64)  // 93248 bytes -> 2 CTAs/SM

// ---------------- device scratch ----------------
__device__ uint2    g_xcp[NN*XCP];      // split bf16 pairs {hi,lo}
__device__ float    g_acc[BG*HL];       // lin1 split-K accumulator
__device__ unsigned g_wh[3*64*128];     // conv W hi plane [L][k2][n], zero-padded
__device__ unsigned g_wl[3*64*128];     // conv W lo plane
__device__ uint2    g_l1w[17280*64];    // lin1 W pairs [k2][n]
__device__ unsigned g_done = 0;         // lin1 completion counter (self-resetting)

// ---------------- helpers ----------------
__device__ __forceinline__ void f2bf2(float v0, float v1, unsigned &h, unsigned &l) {
    __nv_bfloat16 h0 = __float2bfloat16(v0), h1 = __float2bfloat16(v1);
    float r0 = v0 - __bfloat162float(h0);
    float r1 = v1 - __bfloat162float(h1);
    __nv_bfloat16 l0 = __float2bfloat16(r0), l1 = __float2bfloat16(r1);
    h = ((unsigned)__bfloat16_as_ushort(h1) << 16) | (unsigned)__bfloat16_as_ushort(h0);
    l = ((unsigned)__bfloat16_as_ushort(l1) << 16) | (unsigned)__bfloat16_as_ushort(l0);
}
__device__ __forceinline__ void mma16(float* c, const unsigned* a, const unsigned* b) {
    asm volatile("mma.sync.aligned.m16n8k16.row.col.f32.bf16.bf16.f32 "
        "{%0,%1,%2,%3}, {%4,%5,%6,%7}, {%8,%9}, {%0,%1,%2,%3};"
        : "+f"(c[0]), "+f"(c[1]), "+f"(c[2]), "+f"(c[3])
        : "r"(a[0]), "r"(a[1]), "r"(a[2]), "r"(a[3]), "r"(b[0]), "r"(b[1]));
}
__device__ __forceinline__ void mma3u(float* c, const uint2* a, const uint2* b) {
    unsigned ah[4] = {a[0].x, a[1].x, a[2].x, a[3].x};
    unsigned al[4] = {a[0].y, a[1].y, a[2].y, a[3].y};
    unsigned bh[2] = {b[0].x, b[1].x};
    unsigned bl[2] = {b[0].y, b[1].y};
    mma16(c, ah, bh);
    mma16(c, ah, bl);
    mma16(c, al, bh);
}
__device__ __forceinline__ void ldsm4(unsigned* r, unsigned addr) {
    asm volatile("ldmatrix.sync.aligned.m8n8.x4.shared.b16 {%0,%1,%2,%3}, [%4];"
        : "=r"(r[0]), "=r"(r[1]), "=r"(r[2]), "=r"(r[3]) : "r"(addr));
}

// ================= weight pre-split =================
__global__ void k_prew(const float* __restrict__ W1, const float* __restrict__ W2,
                       const float* __restrict__ W3, const float* __restrict__ l1w) {
    int i = blockIdx.x*blockDim.x + threadIdx.x;
    if (i < 3*64*128) {
        int L = i >> 13;
        int r = i & 8191;
        int k2 = r >> 7, n = r & 127;
        const float* W = (L == 0) ? W1 : (L == 1) ? W2 : W3;
        int KW = (L == 0) ? 90 : 128;
        int k = 2*k2;
        float v0 = (k     < KW) ? W[k*HH + n]     : 0.0f;
        float v1 = (k + 1 < KW) ? W[(k+1)*HH + n] : 0.0f;
        unsigned h, l; f2bf2(v0, v1, h, l);
        g_wh[i] = h; g_wl[i] = l;
    } else {
        int j = i - 3*64*128;
        if (j < 17280*64) {
            int k2 = j >> 6, n = j & 63;
            unsigned h, l;
            f2bf2(l1w[(2*k2)*HL + n], l1w[(2*k2+1)*HL + n], h, l);
            g_l1w[j] = make_uint2(h, l);
        }
    }
}

// ================= fused per-graph 3-layer GCN =================
__global__ void __launch_bounds__(256, 2) k_fused(
    const float* __restrict__ x, const float* __restrict__ eattr,
    const int* __restrict__ ei,
    const float* __restrict__ b1, const float* __restrict__ b2,
    const float* __restrict__ b3) {
    extern __shared__ char sm[];
    float*    sdeg = (float*)sm;               // 96 @0
    float*    sdis = (float*)(sm + 512);       // 96 @512
    unsigned* AaWH = (unsigned*)(sm + OFF_A0); // A hi: word [m][k2<48], 52 w/row
    unsigned* AaWL = (unsigned*)(sm + OFF_A1);
    unsigned* HbH  = (unsigned*)(sm + OFF_U);                 // [k2=48][n=128] stride NP
    unsigned* HbL  = (unsigned*)(sm + OFF_U + 26112);
    unsigned* TaWH = (unsigned*)(sm + OFF_U);                 // Ta hi: word [m][k2<64], 68 w/row
    unsigned* TaWL = (unsigned*)(sm + OFF_U + SZ_TA);
    float*    F    = (float*)(sm + OFF_U);                    // [96][MPF] fp32 (prologue only)

    const int g = blockIdx.x, t = threadIdx.x, lane = t & 31, wid = t >> 5;
    const int wm = wid >> 2, wn = wid & 3;      // 2 x 4 warps; warp tile 48x32
    const int gid = lane >> 2, tig = lane & 3;
    const int eb = g * EPG;

    const unsigned aBaseH  = (unsigned)__cvta_generic_to_shared(sm + OFF_A0);
    const unsigned aBaseL  = (unsigned)__cvta_generic_to_shared(sm + OFF_A1);
    const unsigned taBaseH = (unsigned)__cvta_generic_to_shared(sm + OFF_U);
    const unsigned taBaseL = taBaseH + SZ_TA;
    const int rk104 = ((lane & 15)*104 + (lane >> 4)*8) * 2;
    const int rk136 = ((lane & 15)*136 + (lane >> 4)*8) * 2;

    if (t < HL) g_acc[g*HL + t] = 0.0f;

    // ---- prologue: dense normalized adjacency in F (aliases U) ----
    for (int i = t; i < 96*MPF; i += 256) F[i] = 0.0f;
    if (t < 96) sdeg[t] = 1.0f;
    __syncthreads();
    for (int e = t; e < EPG; e += 256)
        atomicAdd(&sdeg[ei[EE + eb + e] - g*NODES], eattr[eb + e]);
    __syncthreads();
    if (t < 96) sdis[t] = rsqrtf(sdeg[t]);
    __syncthreads();
    for (int e = t; e < EPG; e += 256) {
        int s = ei[eb + e] - g*NODES;
        int d = ei[EE + eb + e] - g*NODES;
        atomicAdd(&F[d*MPF + s], sdis[s] * eattr[eb + e] * sdis[d]);
    }
    if (t < NODES) atomicAdd(&F[t*MPF + t], sdis[t]*sdis[t]);
    __syncthreads();
    // ---- A row-major pairs: word [m][k2] ----
    for (int i = t; i < 96*48; i += 256) {
        int m = i / 48, k2 = i - 48*m;
        unsigned h, l; f2bf2(F[m*MPF + 2*k2], F[m*MPF + 2*k2 + 1], h, l);
        AaWH[m*52 + k2] = h; AaWL[m*52 + k2] = l;
    }
    __syncthreads();   // F fully consumed before Hb0 overwrites U
    // ---- Hb0 = x^T pairs [k2=node/2][n=feat] ----
    for (int i = t; i < 48*128; i += 256) {
        int k2 = i >> 7, n = i & 127;
        int n0 = 2*k2, n1 = n0 + 1;
        float v0 = (n < 90 && n0 < 90) ? x[((long)g*NODES + n0)*90 + n] : 0.0f;
        float v1 = (n < 90 && n1 < 90) ? x[((long)g*NODES + n1)*90 + n] : 0.0f;
        unsigned h, l; f2bf2(v0, v1, h, l);
        HbH[k2*NP + n] = h; HbL[k2*NP + n] = l;
    }

    const float* bs[3]  = {b1, b2, b3};
    const int    KT2s[3] = {6, 8, 8};
    float acc[3][4][4];

    for (int L = 0; L < 3; L++) {
        __syncthreads();   // Hb ready
        // ======== GEMM1: T = A @ Hb, K=96 (A via LDSM) ========
        #pragma unroll
        for (int i = 0; i < 3; i++)
            #pragma unroll
            for (int j = 0; j < 4; j++)
                #pragma unroll
                for (int q = 0; q < 4; q++) acc[i][j][q] = 0.0f;
        for (int kt = 0; kt < 6; kt++) {
            unsigned a_h[3][4], a_l[3][4];
            #pragma unroll
            for (int i = 0; i < 3; i++) {
                int mo = (wm*48 + i*16)*208 + kt*32;
                ldsm4(a_h[i], aBaseH + mo + rk104);
                ldsm4(a_l[i], aBaseL + mo + rk104);
            }
            int s0 = (kt*8 + tig)*NP, s4 = s0 + 4*NP;
            #pragma unroll
            for (int j = 0; j < 4; j++) {
                int n = wn*32 + j*8;
                unsigned b_h[2] = { HbH[s0 + n+gid], HbH[s4 + n+gid] };
                unsigned b_l[2] = { HbL[s0 + n+gid], HbL[s4 + n+gid] };
                #pragma unroll
                for (int i = 0; i < 3; i++) {
                    mma16(acc[i][j], a_h[i], b_h);
                    mma16(acc[i][j], a_h[i], b_l);
                    mma16(acc[i][j], a_l[i], b_h);
                }
            }
        }
        __syncthreads();   // all Hb reads done; U reusable
        // ---- T -> Ta row-major pairs: word [m][k2=feat/2] ----
        #pragma unroll
        for (int j = 0; j < 4; j++) {
            int n2 = wn*16 + j*4 + tig;
            #pragma unroll
            for (int i = 0; i < 3; i++) {
                int m = wm*48 + i*16 + gid;
                unsigned h, l;
                f2bf2(acc[i][j][0], acc[i][j][1], h, l);
                TaWH[m*68 + n2] = h; TaWL[m*68 + n2] = l;
                f2bf2(acc[i][j][2], acc[i][j][3], h, l);
                TaWH[(m+8)*68 + n2] = h; TaWL[(m+8)*68 + n2] = l;
            }
        }
        __syncthreads();   // Ta ready
        // ======== GEMM2: H = Ta @ W  (W fragments LDG, register double-buffer) ========
        #pragma unroll
        for (int i = 0; i < 3; i++)
            #pragma unroll
            for (int j = 0; j < 4; j++)
                #pragma unroll
                for (int q = 0; q < 4; q++) acc[i][j][q] = 0.0f;
        const unsigned* WhP = g_wh + L*8192;
        const unsigned* WlP = g_wl + L*8192;
        const int KT2 = KT2s[L];
        unsigned pb_h[4][2], pb_l[4][2];     // prefetch buffer
        auto loadb = [&](int kt) {
            int w0 = (kt*8 + tig)*128, w4 = w0 + 4*128;
            #pragma unroll
            for (int j = 0; j < 4; j++) {
                int n = wn*32 + j*8 + gid;
                pb_h[j][0] = WhP[w0 + n]; pb_h[j][1] = WhP[w4 + n];
                pb_l[j][0] = WlP[w0 + n]; pb_l[j][1] = WlP[w4 + n];
            }
        };
        loadb(0);
        for (int kt = 0; kt < KT2; kt++) {
            unsigned b_h[4][2], b_l[4][2];
            #pragma unroll
            for (int j = 0; j < 4; j++) {
                b_h[j][0] = pb_h[j][0]; b_h[j][1] = pb_h[j][1];
                b_l[j][0] = pb_l[j][0]; b_l[j][1] = pb_l[j][1];
            }
            if (kt + 1 < KT2) loadb(kt + 1);   // LDGs overlap MMA block below
            unsigned a_h[3][4], a_l[3][4];
            #pragma unroll
            for (int i = 0; i < 3; i++) {
                int mo = (wm*48 + i*16)*272 + kt*32;
                ldsm4(a_h[i], taBaseH + mo + rk136);
                ldsm4(a_l[i], taBaseL + mo + rk136);
            }
            #pragma unroll
            for (int j = 0; j < 4; j++) {
                #pragma unroll
                for (int i = 0; i < 3; i++) {
                    mma16(acc[i][j], a_h[i], b_h[j]);
                    mma16(acc[i][j], a_h[i], b_l[j]);
                    mma16(acc[i][j], a_l[i], b_h[j]);
                }
            }
        }
        __syncthreads();   // Ta reads done before Hb-next overwrites U
        // ---- epilogue: relu(+bias) -> g_xcp; next Hb via shuffles ----
        const float* bias = bs[L];
        #pragma unroll
        for (int i = 0; i < 3; i++) {
            #pragma unroll
            for (int j = 0; j < 4; j++) {
                int m = wm*48 + i*16 + gid;
                int n = wn*32 + j*8 + 2*tig;
                float b0 = bias[n], b1 = bias[n+1];
                float v0 = fmaxf(acc[i][j][0] + b0, 0.0f);
                float v1 = fmaxf(acc[i][j][1] + b1, 0.0f);
                float v2 = fmaxf(acc[i][j][2] + b0, 0.0f);
                float v3 = fmaxf(acc[i][j][3] + b1, 0.0f);
                int p2 = L*64 + (n >> 1);
                if (m < NODES) {
                    unsigned h, l; f2bf2(v0, v1, h, l);
                    g_xcp[((long)g*NODES + m)*XCP + p2] = make_uint2(h, l);
                }
                if (m + 8 < NODES) {
                    unsigned h, l; f2bf2(v2, v3, h, l);
                    g_xcp[((long)g*NODES + m + 8)*XCP + p2] = make_uint2(h, l);
                }
                if (L < 2) {
                    float q0 = __shfl_down_sync(0xffffffffu, v0, 4);
                    float q1 = __shfl_down_sync(0xffffffffu, v1, 4);
                    float q2 = __shfl_down_sync(0xffffffffu, v2, 4);
                    float q3 = __shfl_down_sync(0xffffffffu, v3, 4);
                    if (!(gid & 1)) {   // even gid owns node pair (m, m+1)
                        int k2 = wm*24 + i*8 + (gid >> 1);
                        unsigned h, l;
                        f2bf2(v0, q0, h, l); HbH[k2*NP + n]       = h; HbL[k2*NP + n]       = l;
                        f2bf2(v1, q1, h, l); HbH[k2*NP + n + 1]   = h; HbL[k2*NP + n + 1]   = l;
                        f2bf2(v2, q2, h, l); HbH[(k2+4)*NP + n]   = h; HbL[(k2+4)*NP + n]   = l;
                        f2bf2(v3, q3, h, l); HbH[(k2+4)*NP + n+1] = h; HbL[(k2+4)*NP + n+1] = l;
                    }
                }
            }
        }
    }
}

// ================= lin1 (single wave) + fused final epilogue =================
#define L1CTAS (4*72)
__global__ void __launch_bounds__(256, 2) k_lin1(
    const float* __restrict__ b1, const float* __restrict__ W2,
    const float* __restrict__ b2, float* __restrict__ out) {
    __shared__ uint2 As[2][8][SBL];
    __shared__ uint2 Bs[2][8][68];
    __shared__ unsigned s_last;
    const int t = threadIdx.x, lane = t & 31, wid = t >> 5;
    const int wm = wid >> 1, wn = wid & 1;
    const int gid = lane >> 2, tig = lane & 3;
    const int row0   = blockIdx.x * 128;
    const int kbase2 = blockIdx.y * 240;     // pair units
    const int KT = 30;

    const int am  = t >> 1;
    const int ak0 = (t & 1) * 4;
    const int bk0 = t >> 5;
    const int bn0 = (t*2) & 63;

    uint4 rA0, rA1, rB;
    auto load_tile = [&](int kt) {
        const uint2* p = &g_xcp[(long)(row0 + am)*LDA1P + kbase2 + kt*8 + ak0];
        rA0 = *(const uint4*)p;
        rA1 = *(const uint4*)(p + 2);
        rB  = *(const uint4*)&g_l1w[(kbase2 + kt*8 + bk0)*64 + bn0];
    };

    float acc[2][4][4];
    #pragma unroll
    for (int i = 0; i < 2; i++)
        #pragma unroll
        for (int j = 0; j < 4; j++)
            #pragma unroll
            for (int q = 0; q < 4; q++) acc[i][j][q] = 0.0f;

    load_tile(0);
    for (int kt = 0; kt < KT; kt++) {
        int buf = kt & 1;
        As[buf][ak0  ][am] = make_uint2(rA0.x, rA0.y);
        As[buf][ak0+1][am] = make_uint2(rA0.z, rA0.w);
        As[buf][ak0+2][am] = make_uint2(rA1.x, rA1.y);
        As[buf][ak0+3][am] = make_uint2(rA1.z, rA1.w);
        *(uint4*)&Bs[buf][bk0][bn0] = rB;
        __syncthreads();
        if (kt + 1 < KT) load_tile(kt + 1);

        uint2 a[2][4];
        #pragma unroll
        for (int i = 0; i < 2; i++) {
            int m = wm*32 + i*16;
            a[i][0] = As[buf][tig  ][m+gid]; a[i][1] = As[buf][tig  ][m+gid+8];
            a[i][2] = As[buf][tig+4][m+gid]; a[i][3] = As[buf][tig+4][m+gid+8];
        }
        #pragma unroll
        for (int j = 0; j < 4; j++) {
            int n = wn*32 + j*8;
            uint2 b[2] = { Bs[buf][tig][n+gid], Bs[buf][tig+4][n+gid] };
            #pragma unroll
            for (int i = 0; i < 2; i++) mma3u(acc[i][j], a[i], b);
        }
    }
    #pragma unroll
    for (int j = 0; j < 4; j++) {
        int n = wn*32 + j*8 + 2*tig;
        #pragma unroll
        for (int i = 0; i < 2; i++) {
            int r = row0 + wm*32 + i*16 + gid;
            atomicAdd(&g_acc[r*HL + n],         acc[i][j][0]);
            atomicAdd(&g_acc[r*HL + n + 1],     acc[i][j][1]);
            atomicAdd(&g_acc[(r+8)*HL + n],     acc[i][j][2]);
            atomicAdd(&g_acc[(r+8)*HL + n + 1], acc[i][j][3]);
        }
    }
    // ---- last CTA performs the final epilogue for all graphs ----
    __threadfence();
    __syncthreads();
    if (t == 0) {
        unsigned v = atomicAdd(&g_done, 1u);
        s_last = (v == L1CTAS - 1) ? 1u : 0u;
    }
    __syncthreads();
    if (s_last) {
        __threadfence();   // acquire all g_acc writes
        int w0 = t >> 5;   // warp id 0..7
        for (int w = w0; w < BG; w += 8) {
            float h0 = fmaxf(g_acc[w*HL + lane]      + b1[lane],      0.0f);
            float h1 = fmaxf(g_acc[w*HL + lane + 32] + b1[lane + 32], 0.0f);
            float l0 = h0*W2[lane*2]     + h1*W2[(lane+32)*2];
            float l1 = h0*W2[lane*2 + 1] + h1*W2[(lane+32)*2 + 1];
            #pragma unroll
            for (int o = 16; o > 0; o >>= 1) {
                l0 += __shfl_xor_sync(0xffffffffu, l0, o);
                l1 += __shfl_xor_sync(0xffffffffu, l1, o);
            }
            if (lane == 0) {
                l0 += b2[0]; l1 += b2[1];
                float m = fmaxf(l0, l1);
                float lse = m + logf(expf(l0 - m) + expf(l1 - m));
                out[w*2 + 0] = l0 - lse;
                out[w*2 + 1] = l1 - lse;
            }
        }
        __syncthreads();
        if (t == 0) g_done = 0;   // reset for next graph replay
    }
}

// ================= launch =================
extern "C" void kernel_launch(void* const* d_in, const int* in_sizes, int n_in,
                              void* d_out, int out_size) {
    const float* x      = (const float*)d_in[0];
    const float* eattr  = (const float*)d_in[1];
    const float* W1     = (const float*)d_in[2];
    const float* b1     = (const float*)d_in[3];
    const float* W2     = (const float*)d_in[4];
    const float* b2     = (const float*)d_in[5];
    const float* W3     = (const float*)d_in[6];
    const float* b3     = (const float*)d_in[7];
    const float* lin1W  = (const float*)d_in[8];
    const float* lin1b  = (const float*)d_in[9];
    const float* lin2W  = (const float*)d_in[10];
    const float* lin2b  = (const float*)d_in[11];
    const int*   eidx   = (const int*)d_in[12];
    float*       out    = (float*)d_out;

    static int attr_set = 0;
    if (!attr_set) {
        cudaFuncSetAttribute(k_fused, cudaFuncAttributeMaxDynamicSharedMemorySize, SMEMB);
        attr_set = 1;
    }

    const int NPREW = 3*64*128 + 17280*64;
    k_prew<<<(NPREW + 255)/256, 256>>>(W1, W2, W3, lin1W);
    k_fused<<<BG, 256, SMEMB>>>(x, eattr, eidx, b1, b2, b3);
    dim3 g1(BG/128, 72);   // KC = 240 pairs -> 288 CTAs = one wave
    k_lin1<<<g1, 256>>>(lin1b, lin2W, lin2b, out);
}

// round 17
// speedup vs baseline: 1.1819x; 1.1819x over previous
#include <cuda_runtime.h>
#include <cuda_bf16.h>
#include <math.h>

#define NN     46080
#define EE     737280
#define BG     512
#define NODES  90
#define EPG    1440
#define HH     128
#define HL     64
#define XCP    192          // xc pairs per node (384 feats / 2)
#define LDA1P  (NODES*XCP)  // 17280 pairs per graph row

#define MPF 104             // fp32 stride for F scratch
#define NP  136             // u32 stride for Hb [k2][n]
#define SBL 132             // uint2 stride in k_lin1 As

// A  : row-major bf16 [m<96][k<96],  row stride 104 halfwords
// Ta : row-major bf16 [m<96][k<128], row stride 136 halfwords
#define OFF_A0  1024
#define SZ_A    (96*104*2)           // 19968 per plane
#define OFF_A1  (OFF_A0 + SZ_A)
#define OFF_U   (OFF_A1 + SZ_A)      // 40960
#define SZ_TA   (96*136*2)           // 26112 per plane
#define SZ_U    (2*SZ_TA)            // 52224
#define SMEMB   (OFF_U + SZ_U + 64)  // 93248 bytes -> 2 CTAs/SM

// ---------------- device scratch ----------------
__device__ uint2    g_xcp[NN*XCP];      // split bf16 pairs {hi,lo}
__device__ float    g_acc[BG*HL];       // lin1 split-K accumulator
__device__ unsigned g_wh[3*64*128];     // conv W hi plane [L][k2][n], zero-padded
__device__ unsigned g_wl[3*64*128];     // conv W lo plane

// ---------------- helpers ----------------
__device__ __forceinline__ void f2bf2(float v0, float v1, unsigned &h, unsigned &l) {
    __nv_bfloat16 h0 = __float2bfloat16(v0), h1 = __float2bfloat16(v1);
    float r0 = v0 - __bfloat162float(h0);
    float r1 = v1 - __bfloat162float(h1);
    __nv_bfloat16 l0 = __float2bfloat16(r0), l1 = __float2bfloat16(r1);
    h = ((unsigned)__bfloat16_as_ushort(h1) << 16) | (unsigned)__bfloat16_as_ushort(h0);
    l = ((unsigned)__bfloat16_as_ushort(l1) << 16) | (unsigned)__bfloat16_as_ushort(l0);
}
__device__ __forceinline__ void mma16(float* c, const unsigned* a, const unsigned* b) {
    asm volatile("mma.sync.aligned.m16n8k16.row.col.f32.bf16.bf16.f32 "
        "{%0,%1,%2,%3}, {%4,%5,%6,%7}, {%8,%9}, {%0,%1,%2,%3};"
        : "+f"(c[0]), "+f"(c[1]), "+f"(c[2]), "+f"(c[3])
        : "r"(a[0]), "r"(a[1]), "r"(a[2]), "r"(a[3]), "r"(b[0]), "r"(b[1]));
}
__device__ __forceinline__ void mma3u(float* c, const uint2* a, const uint2* b) {
    unsigned ah[4] = {a[0].x, a[1].x, a[2].x, a[3].x};
    unsigned al[4] = {a[0].y, a[1].y, a[2].y, a[3].y};
    unsigned bh[2] = {b[0].x, b[1].x};
    unsigned bl[2] = {b[0].y, b[1].y};
    mma16(c, ah, bh);
    mma16(c, ah, bl);
    mma16(c, al, bh);
}
__device__ __forceinline__ void ldsm4(unsigned* r, unsigned addr) {
    asm volatile("ldmatrix.sync.aligned.m8n8.x4.shared.b16 {%0,%1,%2,%3}, [%4];"
        : "=r"(r[0]), "=r"(r[1]), "=r"(r[2]), "=r"(r[3]) : "r"(addr));
}

// ================= conv weight pre-split (tiny) =================
__global__ void k_prew(const float* __restrict__ W1, const float* __restrict__ W2,
                       const float* __restrict__ W3) {
    int i = blockIdx.x*blockDim.x + threadIdx.x;
    if (i >= 3*64*128) return;
    int L = i >> 13;
    int r = i & 8191;
    int k2 = r >> 7, n = r & 127;
    const float* W = (L == 0) ? W1 : (L == 1) ? W2 : W3;
    int KW = (L == 0) ? 90 : 128;
    int k = 2*k2;
    float v0 = (k     < KW) ? W[k*HH + n]     : 0.0f;
    float v1 = (k + 1 < KW) ? W[(k+1)*HH + n] : 0.0f;
    unsigned h, l; f2bf2(v0, v1, h, l);
    g_wh[i] = h; g_wl[i] = l;
}

// ================= fused per-graph 3-layer GCN (R14 config) =================
__global__ void __launch_bounds__(256, 2) k_fused(
    const float* __restrict__ x, const float* __restrict__ eattr,
    const int* __restrict__ ei,
    const float* __restrict__ b1, const float* __restrict__ b2,
    const float* __restrict__ b3) {
    extern __shared__ char sm[];
    float*    sdeg = (float*)sm;               // 96 @0
    float*    sdis = (float*)(sm + 512);       // 96 @512
    unsigned* AaWH = (unsigned*)(sm + OFF_A0); // A hi: word [m][k2<48], 52 w/row
    unsigned* AaWL = (unsigned*)(sm + OFF_A1);
    unsigned* HbH  = (unsigned*)(sm + OFF_U);                 // [k2=48][n=128] stride NP
    unsigned* HbL  = (unsigned*)(sm + OFF_U + 26112);
    unsigned* TaWH = (unsigned*)(sm + OFF_U);                 // Ta hi: word [m][k2<64], 68 w/row
    unsigned* TaWL = (unsigned*)(sm + OFF_U + SZ_TA);
    float*    F    = (float*)(sm + OFF_U);                    // [96][MPF] fp32 (prologue only)

    const int g = blockIdx.x, t = threadIdx.x, lane = t & 31, wid = t >> 5;
    const int wm = wid >> 2, wn = wid & 3;      // 2 x 4 warps; warp tile 48x32
    const int gid = lane >> 2, tig = lane & 3;
    const int eb = g * EPG;

    const unsigned aBaseH  = (unsigned)__cvta_generic_to_shared(sm + OFF_A0);
    const unsigned aBaseL  = (unsigned)__cvta_generic_to_shared(sm + OFF_A1);
    const unsigned taBaseH = (unsigned)__cvta_generic_to_shared(sm + OFF_U);
    const unsigned taBaseL = taBaseH + SZ_TA;
    const int rk104 = ((lane & 15)*104 + (lane >> 4)*8) * 2;
    const int rk136 = ((lane & 15)*136 + (lane >> 4)*8) * 2;

    if (t < HL) g_acc[g*HL + t] = 0.0f;

    // ---- prologue: dense normalized adjacency in F (aliases U) ----
    for (int i = t; i < 96*MPF; i += 256) F[i] = 0.0f;
    if (t < 96) sdeg[t] = 1.0f;
    __syncthreads();
    for (int e = t; e < EPG; e += 256)
        atomicAdd(&sdeg[ei[EE + eb + e] - g*NODES], eattr[eb + e]);
    __syncthreads();
    if (t < 96) sdis[t] = rsqrtf(sdeg[t]);
    __syncthreads();
    for (int e = t; e < EPG; e += 256) {
        int s = ei[eb + e] - g*NODES;
        int d = ei[EE + eb + e] - g*NODES;
        atomicAdd(&F[d*MPF + s], sdis[s] * eattr[eb + e] * sdis[d]);
    }
    if (t < NODES) atomicAdd(&F[t*MPF + t], sdis[t]*sdis[t]);
    __syncthreads();
    // ---- A row-major pairs: word [m][k2] ----
    for (int i = t; i < 96*48; i += 256) {
        int m = i / 48, k2 = i - 48*m;
        unsigned h, l; f2bf2(F[m*MPF + 2*k2], F[m*MPF + 2*k2 + 1], h, l);
        AaWH[m*52 + k2] = h; AaWL[m*52 + k2] = l;
    }
    __syncthreads();   // F fully consumed before Hb0 overwrites U
    // ---- Hb0 = x^T pairs [k2=node/2][n=feat] ----
    for (int i = t; i < 48*128; i += 256) {
        int k2 = i >> 7, n = i & 127;
        int n0 = 2*k2, n1 = n0 + 1;
        float v0 = (n < 90 && n0 < 90) ? x[((long)g*NODES + n0)*90 + n] : 0.0f;
        float v1 = (n < 90 && n1 < 90) ? x[((long)g*NODES + n1)*90 + n] : 0.0f;
        unsigned h, l; f2bf2(v0, v1, h, l);
        HbH[k2*NP + n] = h; HbL[k2*NP + n] = l;
    }

    const float* bs[3]  = {b1, b2, b3};
    const int    KT2s[3] = {6, 8, 8};
    float acc[3][4][4];

    for (int L = 0; L < 3; L++) {
        __syncthreads();   // Hb ready
        // ======== GEMM1: T = A @ Hb, K=96 (A via LDSM) ========
        #pragma unroll
        for (int i = 0; i < 3; i++)
            #pragma unroll
            for (int j = 0; j < 4; j++)
                #pragma unroll
                for (int q = 0; q < 4; q++) acc[i][j][q] = 0.0f;
        for (int kt = 0; kt < 6; kt++) {
            unsigned a_h[3][4], a_l[3][4];
            #pragma unroll
            for (int i = 0; i < 3; i++) {
                int mo = (wm*48 + i*16)*208 + kt*32;
                ldsm4(a_h[i], aBaseH + mo + rk104);
                ldsm4(a_l[i], aBaseL + mo + rk104);
            }
            int s0 = (kt*8 + tig)*NP, s4 = s0 + 4*NP;
            #pragma unroll
            for (int j = 0; j < 4; j++) {
                int n = wn*32 + j*8;
                unsigned b_h[2] = { HbH[s0 + n+gid], HbH[s4 + n+gid] };
                unsigned b_l[2] = { HbL[s0 + n+gid], HbL[s4 + n+gid] };
                #pragma unroll
                for (int i = 0; i < 3; i++) {
                    mma16(acc[i][j], a_h[i], b_h);
                    mma16(acc[i][j], a_h[i], b_l);
                    mma16(acc[i][j], a_l[i], b_h);
                }
            }
        }
        __syncthreads();   // all Hb reads done; U reusable
        // ---- T -> Ta row-major pairs: word [m][k2=feat/2] ----
        #pragma unroll
        for (int j = 0; j < 4; j++) {
            int n2 = wn*16 + j*4 + tig;
            #pragma unroll
            for (int i = 0; i < 3; i++) {
                int m = wm*48 + i*16 + gid;
                unsigned h, l;
                f2bf2(acc[i][j][0], acc[i][j][1], h, l);
                TaWH[m*68 + n2] = h; TaWL[m*68 + n2] = l;
                f2bf2(acc[i][j][2], acc[i][j][3], h, l);
                TaWH[(m+8)*68 + n2] = h; TaWL[(m+8)*68 + n2] = l;
            }
        }
        __syncthreads();   // Ta ready
        // ======== GEMM2: H = Ta @ W  (Ta via LDSM; W direct from gmem/L2) ========
        #pragma unroll
        for (int i = 0; i < 3; i++)
            #pragma unroll
            for (int j = 0; j < 4; j++)
                #pragma unroll
                for (int q = 0; q < 4; q++) acc[i][j][q] = 0.0f;
        const unsigned* WhP = g_wh + L*8192;
        const unsigned* WlP = g_wl + L*8192;
        const int KT2 = KT2s[L];
        for (int kt = 0; kt < KT2; kt++) {
            unsigned b_h[4][2], b_l[4][2];
            int w0 = (kt*8 + tig)*128, w4 = w0 + 4*128;
            #pragma unroll
            for (int j = 0; j < 4; j++) {
                int n = wn*32 + j*8 + gid;
                b_h[j][0] = WhP[w0 + n]; b_h[j][1] = WhP[w4 + n];
                b_l[j][0] = WlP[w0 + n]; b_l[j][1] = WlP[w4 + n];
            }
            unsigned a_h[3][4], a_l[3][4];
            #pragma unroll
            for (int i = 0; i < 3; i++) {
                int mo = (wm*48 + i*16)*272 + kt*32;
                ldsm4(a_h[i], taBaseH + mo + rk136);
                ldsm4(a_l[i], taBaseL + mo + rk136);
            }
            #pragma unroll
            for (int j = 0; j < 4; j++) {
                #pragma unroll
                for (int i = 0; i < 3; i++) {
                    mma16(acc[i][j], a_h[i], b_h[j]);
                    mma16(acc[i][j], a_h[i], b_l[j]);
                    mma16(acc[i][j], a_l[i], b_h[j]);
                }
            }
        }
        __syncthreads();   // Ta reads done before Hb-next overwrites U
        // ---- epilogue: relu(+bias) -> g_xcp; next Hb via shuffles ----
        const float* bias = bs[L];
        #pragma unroll
        for (int i = 0; i < 3; i++) {
            #pragma unroll
            for (int j = 0; j < 4; j++) {
                int m = wm*48 + i*16 + gid;
                int n = wn*32 + j*8 + 2*tig;
                float b0 = bias[n], b1 = bias[n+1];
                float v0 = fmaxf(acc[i][j][0] + b0, 0.0f);
                float v1 = fmaxf(acc[i][j][1] + b1, 0.0f);
                float v2 = fmaxf(acc[i][j][2] + b0, 0.0f);
                float v3 = fmaxf(acc[i][j][3] + b1, 0.0f);
                int p2 = L*64 + (n >> 1);
                if (m < NODES) {
                    unsigned h, l; f2bf2(v0, v1, h, l);
                    g_xcp[((long)g*NODES + m)*XCP + p2] = make_uint2(h, l);
                }
                if (m + 8 < NODES) {
                    unsigned h, l; f2bf2(v2, v3, h, l);
                    g_xcp[((long)g*NODES + m + 8)*XCP + p2] = make_uint2(h, l);
                }
                if (L < 2) {
                    float q0 = __shfl_down_sync(0xffffffffu, v0, 4);
                    float q1 = __shfl_down_sync(0xffffffffu, v1, 4);
                    float q2 = __shfl_down_sync(0xffffffffu, v2, 4);
                    float q3 = __shfl_down_sync(0xffffffffu, v3, 4);
                    if (!(gid & 1)) {   // even gid owns node pair (m, m+1)
                        int k2 = wm*24 + i*8 + (gid >> 1);
                        unsigned h, l;
                        f2bf2(v0, q0, h, l); HbH[k2*NP + n]       = h; HbL[k2*NP + n]       = l;
                        f2bf2(v1, q1, h, l); HbH[k2*NP + n + 1]   = h; HbL[k2*NP + n + 1]   = l;
                        f2bf2(v2, q2, h, l); HbH[(k2+4)*NP + n]   = h; HbL[(k2+4)*NP + n]   = l;
                        f2bf2(v3, q3, h, l); HbH[(k2+4)*NP + n+1] = h; HbL[(k2+4)*NP + n+1] = l;
                    }
                }
            }
        }
    }
}

// ================= lin1: single wave, KC=240 pairs; B converted in-kernel =================
__global__ void __launch_bounds__(256, 2) k_lin1(const float* __restrict__ W) {
    __shared__ uint2 As[2][8][SBL];
    __shared__ uint2 Bs[2][8][68];
    const int t = threadIdx.x, lane = t & 31, wid = t >> 5;
    const int wm = wid >> 1, wn = wid & 1;
    const int gid = lane >> 2, tig = lane & 3;
    const int row0   = blockIdx.x * 128;
    const int kbase2 = blockIdx.y * 240;     // pair units
    const int KT = 30;

    const int am  = t >> 1;             // A row (0..127)
    const int ak0 = (t & 1) * 4;        // A pair base within k-tile (0 or 4)
    const int bk2 = (t*2) >> 6;         // B k2 row (0..7)
    const int bn0 = (t*2) & 63;         // B col base

    uint4 rA0, rA1;
    float rB[2][2];
    auto load_tile = [&](int kt) {
        const uint2* p = &g_xcp[(long)(row0 + am)*LDA1P + kbase2 + kt*8 + ak0];
        rA0 = *(const uint4*)p;
        rA1 = *(const uint4*)(p + 2);
        int k = 2*(kbase2 + kt*8 + bk2);
        #pragma unroll
        for (int j = 0; j < 2; j++) {
            rB[j][0] = W[k*HL + bn0 + j];
            rB[j][1] = W[(k+1)*HL + bn0 + j];
        }
    };

    float acc[2][4][4];
    #pragma unroll
    for (int i = 0; i < 2; i++)
        #pragma unroll
        for (int j = 0; j < 4; j++)
            #pragma unroll
            for (int q = 0; q < 4; q++) acc[i][j][q] = 0.0f;

    load_tile(0);
    for (int kt = 0; kt < KT; kt++) {
        int buf = kt & 1;
        As[buf][ak0  ][am] = make_uint2(rA0.x, rA0.y);
        As[buf][ak0+1][am] = make_uint2(rA0.z, rA0.w);
        As[buf][ak0+2][am] = make_uint2(rA1.x, rA1.y);
        As[buf][ak0+3][am] = make_uint2(rA1.z, rA1.w);
        #pragma unroll
        for (int j = 0; j < 2; j++) {
            unsigned h, l; f2bf2(rB[j][0], rB[j][1], h, l);
            Bs[buf][bk2][bn0 + j] = make_uint2(h, l);
        }
        __syncthreads();
        if (kt + 1 < KT) load_tile(kt + 1);

        uint2 a[2][4];
        #pragma unroll
        for (int i = 0; i < 2; i++) {
            int m = wm*32 + i*16;
            a[i][0] = As[buf][tig  ][m+gid]; a[i][1] = As[buf][tig  ][m+gid+8];
            a[i][2] = As[buf][tig+4][m+gid]; a[i][3] = As[buf][tig+4][m+gid+8];
        }
        #pragma unroll
        for (int j = 0; j < 4; j++) {
            int n = wn*32 + j*8;
            uint2 b[2] = { Bs[buf][tig][n+gid], Bs[buf][tig+4][n+gid] };
            #pragma unroll
            for (int i = 0; i < 2; i++) mma3u(acc[i][j], a[i], b);
        }
    }
    #pragma unroll
    for (int j = 0; j < 4; j++) {
        int n = wn*32 + j*8 + 2*tig;
        #pragma unroll
        for (int i = 0; i < 2; i++) {
            int r = row0 + wm*32 + i*16 + gid;
            atomicAdd(&g_acc[r*HL + n],         acc[i][j][0]);
            atomicAdd(&g_acc[r*HL + n + 1],     acc[i][j][1]);
            atomicAdd(&g_acc[(r+8)*HL + n],     acc[i][j][2]);
            atomicAdd(&g_acc[(r+8)*HL + n + 1], acc[i][j][3]);
        }
    }
}

// ================= epilogue: warp per graph =================
__global__ void k_final(const float* __restrict__ b1, const float* __restrict__ W2,
                        const float* __restrict__ b2, float* __restrict__ out) {
    int w = (blockIdx.x*blockDim.x + threadIdx.x) >> 5;   // graph id
    int lane = threadIdx.x & 31;
    if (w >= BG) return;
    float h0 = fmaxf(g_acc[w*HL + lane]      + b1[lane],      0.0f);
    float h1 = fmaxf(g_acc[w*HL + lane + 32] + b1[lane + 32], 0.0f);
    float l0 = h0*W2[lane*2]     + h1*W2[(lane+32)*2];
    float l1 = h0*W2[lane*2 + 1] + h1*W2[(lane+32)*2 + 1];
    #pragma unroll
    for (int o = 16; o > 0; o >>= 1) {
        l0 += __shfl_xor_sync(0xffffffffu, l0, o);
        l1 += __shfl_xor_sync(0xffffffffu, l1, o);
    }
    if (lane == 0) {
        l0 += b2[0]; l1 += b2[1];
        float m = fmaxf(l0, l1);
        float lse = m + logf(expf(l0 - m) + expf(l1 - m));
        out[w*2 + 0] = l0 - lse;
        out[w*2 + 1] = l1 - lse;
    }
}

// ================= launch =================
extern "C" void kernel_launch(void* const* d_in, const int* in_sizes, int n_in,
                              void* d_out, int out_size) {
    const float* x      = (const float*)d_in[0];
    const float* eattr  = (const float*)d_in[1];
    const float* W1     = (const float*)d_in[2];
    const float* b1     = (const float*)d_in[3];
    const float* W2     = (const float*)d_in[4];
    const float* b2     = (const float*)d_in[5];
    const float* W3     = (const float*)d_in[6];
    const float* b3     = (const float*)d_in[7];
    const float* lin1W  = (const float*)d_in[8];
    const float* lin1b  = (const float*)d_in[9];
    const float* lin2W  = (const float*)d_in[10];
    const float* lin2b  = (const float*)d_in[11];
    const int*   eidx   = (const int*)d_in[12];
    float*       out    = (float*)d_out;

    static int attr_set = 0;
    if (!attr_set) {
        cudaFuncSetAttribute(k_fused, cudaFuncAttributeMaxDynamicSharedMemorySize, SMEMB);
        attr_set = 1;
    }

    k_prew<<<(3*64*128 + 255)/256, 256>>>(W1, W2, W3);
    k_fused<<<BG, 256, SMEMB>>>(x, eattr, eidx, b1, b2, b3);
    dim3 g1(BG/128, 72);   // KC = 240 pairs -> 288 CTAs = one wave
    k_lin1<<<g1, 256>>>(lin1W);
    k_final<<<BG/8, 256>>>(lin1b, lin2W, lin2b, out);
}